// round 11
// baseline (speedup 1.0000x reference)
#include <cuda_runtime.h>
#include <cuda_bf16.h>
#include <cstdint>

// nodal_MLP via register-resident mma.sync (bf16 hi/lo 3-term split).
// R8: 12 warps/SM (384 thr), cross-tile gather prefetch, B-frag double buffer.

#define TPB    384
#define NWARP  12
#define NNODE  256
#define AA     64
#define HH     100
#define NT     13      // 13 n-tiles of 8 -> 104 (cols 100..103 zero-padded)
#define W1S    72      // k-stride (elems) for W1 slab: 64 + 8 pad
#define W2S    120     // k-stride for W2/W3: 112 + 8 pad

// SMEM byte offsets (all 16B aligned)
#define OFF_W1HI 0
#define W1_BYTES (104 * W1S * 2)        // 14976
#define OFF_W1LO (OFF_W1HI + W1_BYTES)
#define OFF_W2HI (OFF_W1LO + W1_BYTES)
#define W2_BYTES (104 * W2S * 2)        // 24960
#define OFF_W2LO (OFF_W2HI + W2_BYTES)
#define OFF_W3HI (OFF_W2LO + W2_BYTES)
#define OFF_W3LO (OFF_W3HI + W2_BYTES)
#define OFF_B1   (OFF_W3LO + W2_BYTES)  // 104 floats each
#define OFF_B2   (OFF_B1 + 416)
#define OFF_B3   (OFF_B2 + 416)
#define OFF_W4   (OFF_B3 + 416)
#define OFF_GATE (OFF_W4 + 416)         // 64 floats (sorted order)
#define OFF_IDX  (OFF_GATE + 256)       // 64 ints   (sorted order)
#define OFF_SCR  (OFF_IDX + 256)        // 64 ints raw idx scratch
#define OFF_RANK (OFF_SCR + 256)        // 64 ints: rank of original k
#define OFF_B4   (OFF_RANK + 256)
#define SM_TOTAL (OFF_B4 + 16)

__device__ __forceinline__ uint32_t smem_u32(const void* p) {
    uint32_t a;
    asm("{ .reg .u64 t; cvta.to.shared.u64 t, %1; cvt.u32.u64 %0, t; }" : "=r"(a) : "l"(p));
    return a;
}

// x4: matrices 0,1 from hi slab (lanes 0..15), 2,3 from lo slab (lanes 16..31,
// delta folded into the per-lane offset).
#define LDSM_X4(r0, r1, r2, r3, addr) \
    asm volatile("ldmatrix.sync.aligned.m8n8.x4.shared.b16 {%0,%1,%2,%3}, [%4];" \
                 : "=r"(r0), "=r"(r1), "=r"(r2), "=r"(r3) : "r"(addr))

#define MMA_BF16(c, a, b0, b1) \
    asm volatile("mma.sync.aligned.m16n8k16.row.col.f32.bf16.bf16.f32 " \
                 "{%0,%1,%2,%3}, {%4,%5,%6,%7}, {%8,%9}, {%0,%1,%2,%3};" \
                 : "+f"((c)[0]), "+f"((c)[1]), "+f"((c)[2]), "+f"((c)[3]) \
                 : "r"((a)[0]), "r"((a)[1]), "r"((a)[2]), "r"((a)[3]), "r"(b0), "r"(b1))

__device__ __forceinline__ uint32_t pack_bf2(__nv_bfloat16 a, __nv_bfloat16 b) {
    __nv_bfloat162 t = __halves2bfloat162(a, b);
    return *reinterpret_cast<uint32_t*>(&t);
}
__device__ __forceinline__ void split2(float v0, float v1, uint32_t& hi, uint32_t& lo) {
    __nv_bfloat16 h0 = __float2bfloat16(v0);
    __nv_bfloat16 h1 = __float2bfloat16(v1);
    __nv_bfloat16 l0 = __float2bfloat16(v0 - __bfloat162float(h0));
    __nv_bfloat16 l1 = __float2bfloat16(v1 - __bfloat162float(h1));
    hi = pack_bf2(h0, h1);
    lo = pack_bf2(l0, l1);
}

// One layer: acc[13][4] += A @ W, 3-term bf16 split.
// B fragments double-buffered: LDSM for step s+1 issues before MMAs of step s.
template<int KT, int STRIDE>
__device__ __forceinline__ void mma_layer(float (&acc)[NT][4],
                                          const uint32_t (&Ahi)[7][4],
                                          const uint32_t (&Alo)[7][4],
                                          uint32_t wbase, uint32_t laneoff) {
    uint32_t b0, b1, c0, c1;
    LDSM_X4(b0, b1, c0, c1, wbase + laneoff);
    #pragma unroll
    for (int s = 0; s < KT * NT; s++) {
        const int kt = s / NT, j = s % NT;
        uint32_t nb0 = b0, nb1 = b1, nc0 = c0, nc1 = c1;
        if (s + 1 < KT * NT) {
            const int nkt = (s + 1) / NT, nj = (s + 1) % NT;
            uint32_t rel = (uint32_t)(nj * 8 * STRIDE * 2 + nkt * 32) + laneoff;
            LDSM_X4(nb0, nb1, nc0, nc1, wbase + rel);
        }
        MMA_BF16(acc[j], Ahi[kt], b0, b1);   // ah*bh
        MMA_BF16(acc[j], Alo[kt], b0, b1);   // al*bh
        MMA_BF16(acc[j], Ahi[kt], c0, c1);   // ah*bl
        b0 = nb0; b1 = nb1; c0 = nc0; c1 = nc1;
    }
}

// relu(acc + bias) -> next-layer A fragments (hi/lo), reset acc.
__device__ __forceinline__ void build_A(float (&acc)[NT][4],
                                        uint32_t (&Ahi)[7][4], uint32_t (&Alo)[7][4],
                                        const float* bias, int m2) {
    #pragma unroll
    for (int j = 0; j < NT; j++) {
        float2 b = *reinterpret_cast<const float2*>(bias + 8 * j + m2);
        float v0 = fmaxf(acc[j][0] + b.x, 0.f);
        float v1 = fmaxf(acc[j][1] + b.y, 0.f);
        float v2 = fmaxf(acc[j][2] + b.x, 0.f);
        float v3 = fmaxf(acc[j][3] + b.y, 0.f);
        int kt = j >> 1, o = (j & 1) << 1;
        split2(v0, v1, Ahi[kt][o],     Alo[kt][o]);
        split2(v2, v3, Ahi[kt][o + 1], Alo[kt][o + 1]);
        acc[j][0] = acc[j][1] = acc[j][2] = acc[j][3] = 0.f;
    }
    Ahi[6][2] = Ahi[6][3] = Alo[6][2] = Alo[6][3] = 0u;  // k 104..111 pad
}

// Raw (ungated) gather of 32 values for a 16-row tile into registers.
__device__ __forceinline__ void gather_raw(float (&g)[32], const float* __restrict__ data,
                                           int wt, int n_rows, const int* sidx,
                                           int qrow, int m2) {
    const int r0 = wt * 16 + qrow;
    const int r1 = r0 + 8;
    const bool ok0 = r0 < n_rows, ok1 = r1 < n_rows;
    const float* dr0 = data + (size_t)(ok0 ? r0 : 0) * NNODE;
    const float* dr1 = data + (size_t)(ok1 ? r1 : 0) * NNODE;
    #pragma unroll
    for (int kt = 0; kt < 4; kt++) {
        int k0 = kt * 16 + m2;
        int i0 = sidx[k0], i1 = sidx[k0 + 1], i2 = sidx[k0 + 8], i3 = sidx[k0 + 9];
        g[kt * 8 + 0] = ok0 ? __ldg(dr0 + i0) : 0.f;
        g[kt * 8 + 1] = ok0 ? __ldg(dr0 + i1) : 0.f;
        g[kt * 8 + 2] = ok0 ? __ldg(dr0 + i2) : 0.f;
        g[kt * 8 + 3] = ok0 ? __ldg(dr0 + i3) : 0.f;
        g[kt * 8 + 4] = ok1 ? __ldg(dr1 + i0) : 0.f;
        g[kt * 8 + 5] = ok1 ? __ldg(dr1 + i1) : 0.f;
        g[kt * 8 + 6] = ok1 ? __ldg(dr1 + i2) : 0.f;
        g[kt * 8 + 7] = ok1 ? __ldg(dr1 + i3) : 0.f;
    }
}

extern __shared__ char sm[];

__global__ void __launch_bounds__(TPB, 1) nodal_mlp_hmma(
    const float* __restrict__ data, const float* __restrict__ weights,
    const float* __restrict__ W1, const float* __restrict__ b1,
    const float* __restrict__ W2, const float* __restrict__ b2,
    const float* __restrict__ W3, const float* __restrict__ b3,
    const float* __restrict__ W4, const float* __restrict__ b4,
    const int* __restrict__ data_idx, const int* __restrict__ edge_dir,
    const int* __restrict__ weight_idx,
    float* __restrict__ out, int n_rows)
{
    const int t = threadIdx.x;

    // ---- zero smem ----
    for (int i = t; i < SM_TOTAL / 4; i += TPB)
        reinterpret_cast<uint32_t*>(sm)[i] = 0;
    __syncthreads();

    // ---- sort indices: rank of each original k among data_idx (ties by pos) ----
    int* scr  = reinterpret_cast<int*>(sm + OFF_SCR);
    int* rnk  = reinterpret_cast<int*>(sm + OFF_RANK);
    if (t < AA) scr[t] = data_idx[t];
    __syncthreads();
    if (t < AA) {
        int my = scr[t];
        int r = 0;
        #pragma unroll
        for (int j = 0; j < AA; j++) {
            int o = scr[j];
            r += (o < my) || (o == my && j < t);
        }
        rnk[t] = r;
        reinterpret_cast<int*>(sm + OFF_IDX)[r] = my;
        float g = weights[weight_idx[t]] * (float)edge_dir[t];
        reinterpret_cast<float*>(sm + OFF_GATE)[r] = g > 0.f ? g : 0.f;
    }
    __syncthreads();

    // ---- stage weights (once per CTA); W1 rows permuted by rank ----
    for (int i = t; i < AA * HH; i += TPB) {
        int k = rnk[i / HH], n = i % HH;
        float v = W1[i];
        __nv_bfloat16 h = __float2bfloat16(v);
        __nv_bfloat16 l = __float2bfloat16(v - __bfloat162float(h));
        *reinterpret_cast<__nv_bfloat16*>(sm + OFF_W1HI + (n * W1S + k) * 2) = h;
        *reinterpret_cast<__nv_bfloat16*>(sm + OFF_W1LO + (n * W1S + k) * 2) = l;
    }
    for (int i = t; i < HH * HH; i += TPB) {
        int k = i / HH, n = i % HH;
        int o = (n * W2S + k) * 2;
        float v = W2[i];
        __nv_bfloat16 h = __float2bfloat16(v);
        *reinterpret_cast<__nv_bfloat16*>(sm + OFF_W2HI + o) = h;
        *reinterpret_cast<__nv_bfloat16*>(sm + OFF_W2LO + o) =
            __float2bfloat16(v - __bfloat162float(h));
        v = W3[i];
        h = __float2bfloat16(v);
        *reinterpret_cast<__nv_bfloat16*>(sm + OFF_W3HI + o) = h;
        *reinterpret_cast<__nv_bfloat16*>(sm + OFF_W3LO + o) =
            __float2bfloat16(v - __bfloat162float(h));
    }
    if (t < HH) {
        reinterpret_cast<float*>(sm + OFF_B1)[t] = b1[t];
        reinterpret_cast<float*>(sm + OFF_B2)[t] = b2[t];
        reinterpret_cast<float*>(sm + OFF_B3)[t] = b3[t];
        reinterpret_cast<float*>(sm + OFF_W4)[t] = W4[t];
    }
    if (t == 0) reinterpret_cast<float*>(sm + OFF_B4)[0] = b4[0];
    __syncthreads();

    const uint32_t sb = smem_u32(sm);
    const int lane = t & 31;
    const int warp = t >> 5;
    const int m = lane & 3;
    const int m2 = m * 2;
    const int qrow = lane >> 2;
    // ldmatrix.x4 lane offsets: lanes 0-15 -> hi slab, 16-31 -> lo slab
    const uint32_t loff1 = (uint32_t)(((lane & 7) * W1S + ((lane >> 3) & 1) * 8) * 2
                                      + ((lane >> 4) & 1) * W1_BYTES);
    const uint32_t loff2 = (uint32_t)(((lane & 7) * W2S + ((lane >> 3) & 1) * 8) * 2
                                      + ((lane >> 4) & 1) * W2_BYTES);

    const float* gate = reinterpret_cast<const float*>(sm + OFF_GATE);
    const int*   sidx = reinterpret_cast<const int*>(sm + OFF_IDX);
    const float* sb1  = reinterpret_cast<const float*>(sm + OFF_B1);
    const float* sb2  = reinterpret_cast<const float*>(sm + OFF_B2);
    const float* sb3  = reinterpret_cast<const float*>(sm + OFF_B3);
    const float* sw4  = reinterpret_cast<const float*>(sm + OFF_W4);
    const float  b4v  = reinterpret_cast<const float*>(sm + OFF_B4)[0];

    const int n_wt = (n_rows + 15) >> 4;         // 16-row warp tiles
    const int gw = blockIdx.x * NWARP + warp;
    const int wstride = gridDim.x * NWARP;

    float g[32];
    if (gw < n_wt) gather_raw(g, data, gw, n_rows, sidx, qrow, m2);

    for (int wt = gw; wt < n_wt; wt += wstride) {
        const int r0 = wt * 16 + qrow;
        const int r1 = r0 + 8;
        const bool ok0 = r0 < n_rows, ok1 = r1 < n_rows;

        uint32_t Ahi[7][4], Alo[7][4];

        // ---- X fragments from prefetched raw values * gate ----
        #pragma unroll
        for (int kt = 0; kt < 4; kt++) {
            int k0 = kt * 16 + m2;
            float g0 = gate[k0], g1 = gate[k0 + 1], g2 = gate[k0 + 8], g3 = gate[k0 + 9];
            split2(g[kt*8+0] * g0, g[kt*8+1] * g1, Ahi[kt][0], Alo[kt][0]);
            split2(g[kt*8+4] * g0, g[kt*8+5] * g1, Ahi[kt][1], Alo[kt][1]);
            split2(g[kt*8+2] * g2, g[kt*8+3] * g3, Ahi[kt][2], Alo[kt][2]);
            split2(g[kt*8+6] * g2, g[kt*8+7] * g3, Ahi[kt][3], Alo[kt][3]);
        }

        float acc[NT][4];
        #pragma unroll
        for (int j = 0; j < NT; j++)
            acc[j][0] = acc[j][1] = acc[j][2] = acc[j][3] = 0.f;

        // ---- layer 1 ----
        mma_layer<4, W1S>(acc, Ahi, Alo, sb + OFF_W1HI, loff1);

        // ---- prefetch next tile's raw gather (hides under layers 2-3) ----
        const int nwt = wt + wstride;
        if (nwt < n_wt) gather_raw(g, data, nwt, n_rows, sidx, qrow, m2);

        build_A(acc, Ahi, Alo, sb1, m2);
        mma_layer<7, W2S>(acc, Ahi, Alo, sb + OFF_W2HI, loff2);
        build_A(acc, Ahi, Alo, sb2, m2);
        mma_layer<7, W2S>(acc, Ahi, Alo, sb + OFF_W3HI, loff2);

        // ---- layer 4: relu + dot + quad reduce ----
        float s0 = 0.f, s1 = 0.f;
        #pragma unroll
        for (int j = 0; j < NT; j++) {
            float2 b = *reinterpret_cast<const float2*>(sb3 + 8 * j + m2);
            float2 w = *reinterpret_cast<const float2*>(sw4 + 8 * j + m2);
            s0 = fmaf(fmaxf(acc[j][0] + b.x, 0.f), w.x, s0);
            s0 = fmaf(fmaxf(acc[j][1] + b.y, 0.f), w.y, s0);
            s1 = fmaf(fmaxf(acc[j][2] + b.x, 0.f), w.x, s1);
            s1 = fmaf(fmaxf(acc[j][3] + b.y, 0.f), w.y, s1);
        }
        s0 += __shfl_xor_sync(0xFFFFFFFFu, s0, 1);
        s0 += __shfl_xor_sync(0xFFFFFFFFu, s0, 2);
        s1 += __shfl_xor_sync(0xFFFFFFFFu, s1, 1);
        s1 += __shfl_xor_sync(0xFFFFFFFFu, s1, 2);
        if (m == 0) {
            if (ok0) out[r0] = s0 + b4v;
            if (ok1) out[r1] = s1 + b4v;
        }
    }
}

extern "C" void kernel_launch(void* const* d_in, const int* in_sizes, int n_in,
                              void* d_out, int out_size)
{
    const float* data       = (const float*)d_in[0];
    const float* weights    = (const float*)d_in[1];
    const float* W1         = (const float*)d_in[2];
    const float* b1         = (const float*)d_in[3];
    const float* W2         = (const float*)d_in[4];
    const float* b2         = (const float*)d_in[5];
    const float* W3         = (const float*)d_in[6];
    const float* b3         = (const float*)d_in[7];
    const float* W4         = (const float*)d_in[8];
    const float* b4         = (const float*)d_in[9];
    const int*   data_idx   = (const int*)d_in[10];
    const int*   edge_dir   = (const int*)d_in[11];
    const int*   weight_idx = (const int*)d_in[12];
    float* out = (float*)d_out;

    const int n_rows = out_size;

    cudaFuncSetAttribute(nodal_mlp_hmma,
                         cudaFuncAttributeMaxDynamicSharedMemorySize, SM_TOTAL);

    nodal_mlp_hmma<<<148, TPB, SM_TOTAL>>>(
        data, weights, W1, b1, W2, b2, W3, b3, W4, b4,
        data_idx, edge_dir, weight_idx, out, n_rows);
}

// round 14
// speedup vs baseline: 1.1072x; 1.1072x over previous
#include <cuda_runtime.h>
#include <cuda_bf16.h>
#include <cstdint>

// nodal_MLP via register-resident mma.sync (bf16 hi/lo 3-term split).
// R12: 2-way j-interleave in MMA stream (acc dependency distance 1 -> 2),
// 4-deep B-fragment ring, packed-cvt split2. TPB back to 256.

#define TPB    256
#define NWARP  8
#define NNODE  256
#define AA     64
#define HH     100
#define NT     13      // 13 n-tiles of 8 -> 104 (cols 100..103 zero-padded)
#define W1S    72      // k-stride (elems) for W1 slab: 64 + 8 pad
#define W2S    120     // k-stride for W2/W3: 112 + 8 pad

// SMEM byte offsets (all 16B aligned)
#define OFF_W1HI 0
#define W1_BYTES (104 * W1S * 2)        // 14976
#define OFF_W1LO (OFF_W1HI + W1_BYTES)
#define OFF_W2HI (OFF_W1LO + W1_BYTES)
#define W2_BYTES (104 * W2S * 2)        // 24960
#define OFF_W2LO (OFF_W2HI + W2_BYTES)
#define OFF_W3HI (OFF_W2LO + W2_BYTES)
#define OFF_W3LO (OFF_W3HI + W2_BYTES)
#define OFF_B1   (OFF_W3LO + W2_BYTES)  // 104 floats each
#define OFF_B2   (OFF_B1 + 416)
#define OFF_B3   (OFF_B2 + 416)
#define OFF_W4   (OFF_B3 + 416)
#define OFF_GATE (OFF_W4 + 416)         // 64 floats (sorted order)
#define OFF_IDX  (OFF_GATE + 256)       // 64 ints   (sorted order)
#define OFF_SCR  (OFF_IDX + 256)        // 64 ints raw idx scratch
#define OFF_RANK (OFF_SCR + 256)        // 64 ints: rank of original k
#define OFF_B4   (OFF_RANK + 256)
#define SM_TOTAL (OFF_B4 + 16)

__device__ __forceinline__ uint32_t smem_u32(const void* p) {
    uint32_t a;
    asm("{ .reg .u64 t; cvta.to.shared.u64 t, %1; cvt.u32.u64 %0, t; }" : "=r"(a) : "l"(p));
    return a;
}

// x4: matrices 0,1 from hi slab (lanes 0..15), 2,3 from lo slab (lanes 16..31,
// delta folded into the per-lane offset).
#define LDSM_X4(r0, r1, r2, r3, addr) \
    asm volatile("ldmatrix.sync.aligned.m8n8.x4.shared.b16 {%0,%1,%2,%3}, [%4];" \
                 : "=r"(r0), "=r"(r1), "=r"(r2), "=r"(r3) : "r"(addr))

#define MMA_BF16(c, a, b0, b1) \
    asm volatile("mma.sync.aligned.m16n8k16.row.col.f32.bf16.bf16.f32 " \
                 "{%0,%1,%2,%3}, {%4,%5,%6,%7}, {%8,%9}, {%0,%1,%2,%3};" \
                 : "+f"((c)[0]), "+f"((c)[1]), "+f"((c)[2]), "+f"((c)[3]) \
                 : "r"((a)[0]), "r"((a)[1]), "r"((a)[2]), "r"((a)[3]), "r"(b0), "r"(b1))

// split (v0,v1) -> packed hi bf16x2 and packed lo bf16x2 (identical math to
// scalar cvt path, fewer instructions).
__device__ __forceinline__ void split2(float v0, float v1, uint32_t& hi, uint32_t& lo) {
    uint32_t h;
    asm("cvt.rn.bf16x2.f32 %0, %1, %2;" : "=r"(h) : "f"(v1), "f"(v0));
    float f0 = __uint_as_float(h << 16);
    float f1 = __uint_as_float(h & 0xFFFF0000u);
    uint32_t l;
    asm("cvt.rn.bf16x2.f32 %0, %1, %2;" : "=r"(l) : "f"(v1 - f1), "f"(v0 - f0));
    hi = h; lo = l;
}

// One layer: acc[13][4] += A @ W, 3-term bf16 split.
// Flattened steps s = kt*NT + j, processed two at a time; same-acc MMAs are
// dependency distance 2 apart. B fragments 4-deep ring (2 live + 2 prefetch).
template<int KT, int STRIDE>
__device__ __forceinline__ void mma_layer(float (&acc)[NT][4],
                                          const uint32_t (&Ahi)[7][4],
                                          const uint32_t (&Alo)[7][4],
                                          uint32_t wbase, uint32_t laneoff) {
    constexpr int S = KT * NT;
    uint32_t A0[4], A1[4], P0[4], P1[4];
    LDSM_X4(A0[0], A0[1], A0[2], A0[3], wbase + laneoff);  // s=0 (j=0,kt=0)
    LDSM_X4(A1[0], A1[1], A1[2], A1[3],
            wbase + (uint32_t)(1 * 8 * STRIDE * 2) + laneoff);  // s=1 (j=1,kt=0)
    P0[0]=P0[1]=P0[2]=P0[3]=0u; P1[0]=P1[1]=P1[2]=P1[3]=0u;
    #pragma unroll
    for (int s = 0; s < S; s += 2) {
        const int j0 = s % NT, kt0 = s / NT;
        const bool has1 = (s + 1) < S;
        const int j1 = has1 ? (s + 1) % NT : 0;
        const int kt1 = has1 ? (s + 1) / NT : 0;
        if (s + 2 < S) {
            const int jn = (s + 2) % NT, ktn = (s + 2) / NT;
            LDSM_X4(P0[0], P0[1], P0[2], P0[3],
                    wbase + (uint32_t)(jn * 8 * STRIDE * 2 + ktn * 32) + laneoff);
        }
        if (s + 3 < S) {
            const int jn = (s + 3) % NT, ktn = (s + 3) / NT;
            LDSM_X4(P1[0], P1[1], P1[2], P1[3],
                    wbase + (uint32_t)(jn * 8 * STRIDE * 2 + ktn * 32) + laneoff);
        }
        MMA_BF16(acc[j0], Ahi[kt0], A0[0], A0[1]);              // ah*bh (s)
        if (has1) MMA_BF16(acc[j1], Ahi[kt1], A1[0], A1[1]);    // ah*bh (s+1)
        MMA_BF16(acc[j0], Alo[kt0], A0[0], A0[1]);              // al*bh (s)
        if (has1) MMA_BF16(acc[j1], Alo[kt1], A1[0], A1[1]);    // al*bh (s+1)
        MMA_BF16(acc[j0], Ahi[kt0], A0[2], A0[3]);              // ah*bl (s)
        if (has1) MMA_BF16(acc[j1], Ahi[kt1], A1[2], A1[3]);    // ah*bl (s+1)
        #pragma unroll
        for (int q = 0; q < 4; q++) { A0[q] = P0[q]; A1[q] = P1[q]; }
    }
}

// relu(acc + bias) -> next-layer A fragments (hi/lo), reset acc.
__device__ __forceinline__ void build_A(float (&acc)[NT][4],
                                        uint32_t (&Ahi)[7][4], uint32_t (&Alo)[7][4],
                                        const float* bias, int m2) {
    #pragma unroll
    for (int j = 0; j < NT; j++) {
        float2 b = *reinterpret_cast<const float2*>(bias + 8 * j + m2);
        float v0 = fmaxf(acc[j][0] + b.x, 0.f);
        float v1 = fmaxf(acc[j][1] + b.y, 0.f);
        float v2 = fmaxf(acc[j][2] + b.x, 0.f);
        float v3 = fmaxf(acc[j][3] + b.y, 0.f);
        int kt = j >> 1, o = (j & 1) << 1;
        split2(v0, v1, Ahi[kt][o],     Alo[kt][o]);
        split2(v2, v3, Ahi[kt][o + 1], Alo[kt][o + 1]);
        acc[j][0] = acc[j][1] = acc[j][2] = acc[j][3] = 0.f;
    }
    Ahi[6][2] = Ahi[6][3] = Alo[6][2] = Alo[6][3] = 0u;  // k 104..111 pad
}

// Raw (ungated) gather of 32 values for a 16-row tile into registers.
__device__ __forceinline__ void gather_raw(float (&g)[32], const float* __restrict__ data,
                                           int wt, int n_rows, const int* sidx,
                                           int qrow, int m2) {
    const int r0 = wt * 16 + qrow;
    const int r1 = r0 + 8;
    const bool ok0 = r0 < n_rows, ok1 = r1 < n_rows;
    const float* dr0 = data + (size_t)(ok0 ? r0 : 0) * NNODE;
    const float* dr1 = data + (size_t)(ok1 ? r1 : 0) * NNODE;
    #pragma unroll
    for (int kt = 0; kt < 4; kt++) {
        int k0 = kt * 16 + m2;
        int i0 = sidx[k0], i1 = sidx[k0 + 1], i2 = sidx[k0 + 8], i3 = sidx[k0 + 9];
        g[kt * 8 + 0] = ok0 ? __ldg(dr0 + i0) : 0.f;
        g[kt * 8 + 1] = ok0 ? __ldg(dr0 + i1) : 0.f;
        g[kt * 8 + 2] = ok0 ? __ldg(dr0 + i2) : 0.f;
        g[kt * 8 + 3] = ok0 ? __ldg(dr0 + i3) : 0.f;
        g[kt * 8 + 4] = ok1 ? __ldg(dr1 + i0) : 0.f;
        g[kt * 8 + 5] = ok1 ? __ldg(dr1 + i1) : 0.f;
        g[kt * 8 + 6] = ok1 ? __ldg(dr1 + i2) : 0.f;
        g[kt * 8 + 7] = ok1 ? __ldg(dr1 + i3) : 0.f;
    }
}

extern __shared__ char sm[];

__global__ void __launch_bounds__(TPB, 1) nodal_mlp_hmma(
    const float* __restrict__ data, const float* __restrict__ weights,
    const float* __restrict__ W1, const float* __restrict__ b1,
    const float* __restrict__ W2, const float* __restrict__ b2,
    const float* __restrict__ W3, const float* __restrict__ b3,
    const float* __restrict__ W4, const float* __restrict__ b4,
    const int* __restrict__ data_idx, const int* __restrict__ edge_dir,
    const int* __restrict__ weight_idx,
    float* __restrict__ out, int n_rows)
{
    const int t = threadIdx.x;

    // ---- zero smem ----
    for (int i = t; i < SM_TOTAL / 4; i += TPB)
        reinterpret_cast<uint32_t*>(sm)[i] = 0;
    __syncthreads();

    // ---- sort indices: rank of each original k among data_idx (ties by pos) ----
    int* scr  = reinterpret_cast<int*>(sm + OFF_SCR);
    int* rnk  = reinterpret_cast<int*>(sm + OFF_RANK);
    if (t < AA) scr[t] = data_idx[t];
    __syncthreads();
    if (t < AA) {
        int my = scr[t];
        int r = 0;
        #pragma unroll
        for (int j = 0; j < AA; j++) {
            int o = scr[j];
            r += (o < my) || (o == my && j < t);
        }
        rnk[t] = r;
        reinterpret_cast<int*>(sm + OFF_IDX)[r] = my;
        float g = weights[weight_idx[t]] * (float)edge_dir[t];
        reinterpret_cast<float*>(sm + OFF_GATE)[r] = g > 0.f ? g : 0.f;
    }
    __syncthreads();

    // ---- stage weights (once per CTA); W1 rows permuted by rank ----
    for (int i = t; i < AA * HH; i += TPB) {
        int k = rnk[i / HH], n = i % HH;
        float v = W1[i];
        __nv_bfloat16 h = __float2bfloat16(v);
        __nv_bfloat16 l = __float2bfloat16(v - __bfloat162float(h));
        *reinterpret_cast<__nv_bfloat16*>(sm + OFF_W1HI + (n * W1S + k) * 2) = h;
        *reinterpret_cast<__nv_bfloat16*>(sm + OFF_W1LO + (n * W1S + k) * 2) = l;
    }
    for (int i = t; i < HH * HH; i += TPB) {
        int k = i / HH, n = i % HH;
        int o = (n * W2S + k) * 2;
        float v = W2[i];
        __nv_bfloat16 h = __float2bfloat16(v);
        *reinterpret_cast<__nv_bfloat16*>(sm + OFF_W2HI + o) = h;
        *reinterpret_cast<__nv_bfloat16*>(sm + OFF_W2LO + o) =
            __float2bfloat16(v - __bfloat162float(h));
        v = W3[i];
        h = __float2bfloat16(v);
        *reinterpret_cast<__nv_bfloat16*>(sm + OFF_W3HI + o) = h;
        *reinterpret_cast<__nv_bfloat16*>(sm + OFF_W3LO + o) =
            __float2bfloat16(v - __bfloat162float(h));
    }
    if (t < HH) {
        reinterpret_cast<float*>(sm + OFF_B1)[t] = b1[t];
        reinterpret_cast<float*>(sm + OFF_B2)[t] = b2[t];
        reinterpret_cast<float*>(sm + OFF_B3)[t] = b3[t];
        reinterpret_cast<float*>(sm + OFF_W4)[t] = W4[t];
    }
    if (t == 0) reinterpret_cast<float*>(sm + OFF_B4)[0] = b4[0];
    __syncthreads();

    const uint32_t sb = smem_u32(sm);
    const int lane = t & 31;
    const int warp = t >> 5;
    const int m = lane & 3;
    const int m2 = m * 2;
    const int qrow = lane >> 2;
    // ldmatrix.x4 lane offsets: lanes 0-15 -> hi slab, 16-31 -> lo slab
    const uint32_t loff1 = (uint32_t)(((lane & 7) * W1S + ((lane >> 3) & 1) * 8) * 2
                                      + ((lane >> 4) & 1) * W1_BYTES);
    const uint32_t loff2 = (uint32_t)(((lane & 7) * W2S + ((lane >> 3) & 1) * 8) * 2
                                      + ((lane >> 4) & 1) * W2_BYTES);

    const float* gate = reinterpret_cast<const float*>(sm + OFF_GATE);
    const int*   sidx = reinterpret_cast<const int*>(sm + OFF_IDX);
    const float* sb1  = reinterpret_cast<const float*>(sm + OFF_B1);
    const float* sb2  = reinterpret_cast<const float*>(sm + OFF_B2);
    const float* sb3  = reinterpret_cast<const float*>(sm + OFF_B3);
    const float* sw4  = reinterpret_cast<const float*>(sm + OFF_W4);
    const float  b4v  = reinterpret_cast<const float*>(sm + OFF_B4)[0];

    const int n_wt = (n_rows + 15) >> 4;         // 16-row warp tiles
    const int gw = blockIdx.x * NWARP + warp;
    const int wstride = gridDim.x * NWARP;

    float g[32];
    if (gw < n_wt) gather_raw(g, data, gw, n_rows, sidx, qrow, m2);

    for (int wt = gw; wt < n_wt; wt += wstride) {
        const int r0 = wt * 16 + qrow;
        const int r1 = r0 + 8;
        const bool ok0 = r0 < n_rows, ok1 = r1 < n_rows;

        uint32_t Ahi[7][4], Alo[7][4];

        // ---- X fragments from prefetched raw values * gate ----
        #pragma unroll
        for (int kt = 0; kt < 4; kt++) {
            int k0 = kt * 16 + m2;
            float g0 = gate[k0], g1 = gate[k0 + 1], g2 = gate[k0 + 8], g3 = gate[k0 + 9];
            split2(g[kt*8+0] * g0, g[kt*8+1] * g1, Ahi[kt][0], Alo[kt][0]);
            split2(g[kt*8+4] * g0, g[kt*8+5] * g1, Ahi[kt][1], Alo[kt][1]);
            split2(g[kt*8+2] * g2, g[kt*8+3] * g3, Ahi[kt][2], Alo[kt][2]);
            split2(g[kt*8+6] * g2, g[kt*8+7] * g3, Ahi[kt][3], Alo[kt][3]);
        }

        float acc[NT][4];
        #pragma unroll
        for (int j = 0; j < NT; j++)
            acc[j][0] = acc[j][1] = acc[j][2] = acc[j][3] = 0.f;

        // ---- layer 1 ----
        mma_layer<4, W1S>(acc, Ahi, Alo, sb + OFF_W1HI, loff1);

        // ---- prefetch next tile's raw gather (hides under layers 2-3) ----
        const int nwt = wt + wstride;
        if (nwt < n_wt) gather_raw(g, data, nwt, n_rows, sidx, qrow, m2);

        build_A(acc, Ahi, Alo, sb1, m2);
        mma_layer<7, W2S>(acc, Ahi, Alo, sb + OFF_W2HI, loff2);
        build_A(acc, Ahi, Alo, sb2, m2);
        mma_layer<7, W2S>(acc, Ahi, Alo, sb + OFF_W3HI, loff2);

        // ---- layer 4: relu + dot + quad reduce ----
        float s0 = 0.f, s1 = 0.f;
        #pragma unroll
        for (int j = 0; j < NT; j++) {
            float2 b = *reinterpret_cast<const float2*>(sb3 + 8 * j + m2);
            float2 w = *reinterpret_cast<const float2*>(sw4 + 8 * j + m2);
            s0 = fmaf(fmaxf(acc[j][0] + b.x, 0.f), w.x, s0);
            s0 = fmaf(fmaxf(acc[j][1] + b.y, 0.f), w.y, s0);
            s1 = fmaf(fmaxf(acc[j][2] + b.x, 0.f), w.x, s1);
            s1 = fmaf(fmaxf(acc[j][3] + b.y, 0.f), w.y, s1);
        }
        s0 += __shfl_xor_sync(0xFFFFFFFFu, s0, 1);
        s0 += __shfl_xor_sync(0xFFFFFFFFu, s0, 2);
        s1 += __shfl_xor_sync(0xFFFFFFFFu, s1, 1);
        s1 += __shfl_xor_sync(0xFFFFFFFFu, s1, 2);
        if (m == 0) {
            if (ok0) out[r0] = s0 + b4v;
            if (ok1) out[r1] = s1 + b4v;
        }
    }
}

extern "C" void kernel_launch(void* const* d_in, const int* in_sizes, int n_in,
                              void* d_out, int out_size)
{
    const float* data       = (const float*)d_in[0];
    const float* weights    = (const float*)d_in[1];
    const float* W1         = (const float*)d_in[2];
    const float* b1         = (const float*)d_in[3];
    const float* W2         = (const float*)d_in[4];
    const float* b2         = (const float*)d_in[5];
    const float* W3         = (const float*)d_in[6];
    const float* b3         = (const float*)d_in[7];
    const float* W4         = (const float*)d_in[8];
    const float* b4         = (const float*)d_in[9];
    const int*   data_idx   = (const int*)d_in[10];
    const int*   edge_dir   = (const int*)d_in[11];
    const int*   weight_idx = (const int*)d_in[12];
    float* out = (float*)d_out;

    const int n_rows = out_size;

    cudaFuncSetAttribute(nodal_mlp_hmma,
                         cudaFuncAttributeMaxDynamicSharedMemorySize, SM_TOTAL);

    nodal_mlp_hmma<<<148, TPB, SM_TOTAL>>>(
        data, weights, W1, b1, W2, b2, W3, b3, W4, b4,
        data_idx, edge_dir, weight_idx, out, n_rows);
}

// round 15
// speedup vs baseline: 1.5287x; 1.3806x over previous
#include <cuda_runtime.h>
#include <cuda_fp16.h>
#include <cstdint>

// nodal_MLP via register-resident mma.sync, fp16 2-term split.
// A (activations) split exactly into ah+al fp16; W rounded once to fp16
// (error 2^-11). 2 MMAs per (kt, n-tile) instead of 3; single W slab halves
// LDSM traffic (one x4 feeds two n-tiles). Sorted gather + prefetch kept.

#define TPB    256
#define NWARP  8
#define NNODE  256
#define AA     64
#define HH     100
#define NT     13      // 13 n-tiles of 8 -> 104 (cols 100..103 zero-padded)
#define W1S    72      // k-stride (elems) for W1 slab: 64 + 8 pad
#define W2S    120     // k-stride for W2/W3: 112 + 8 pad

// SMEM byte offsets (all 16B aligned)
#define OFF_W1   0
#define W1_BYTES (104 * W1S * 2)        // 14976
#define OFF_W2   (OFF_W1 + W1_BYTES)
#define W2_BYTES (104 * W2S * 2)        // 24960
#define OFF_W3   (OFF_W2 + W2_BYTES)
#define OFF_B1   (OFF_W3 + W2_BYTES)    // 104 floats each
#define OFF_B2   (OFF_B1 + 416)
#define OFF_B3   (OFF_B2 + 416)
#define OFF_W4   (OFF_B3 + 416)
#define OFF_GATE (OFF_W4 + 416)         // 64 floats (sorted order)
#define OFF_IDX  (OFF_GATE + 256)       // 64 ints   (sorted order)
#define OFF_SCR  (OFF_IDX + 256)        // 64 ints raw idx scratch
#define OFF_RANK (OFF_SCR + 256)        // 64 ints: rank of original k
#define OFF_B4   (OFF_RANK + 256)
#define SM_TOTAL (OFF_B4 + 16)

__device__ __forceinline__ uint32_t smem_u32(const void* p) {
    uint32_t a;
    asm("{ .reg .u64 t; cvta.to.shared.u64 t, %1; cvt.u32.u64 %0, t; }" : "=r"(a) : "l"(p));
    return a;
}

// x4: 4 consecutive 8x8 b16 matrices = B fragments for TWO adjacent n-tiles
// (j: matrices 0,1 via lanes 0..15; j+1: matrices 2,3 via lanes 16..31).
#define LDSM_X4(r0, r1, r2, r3, addr) \
    asm volatile("ldmatrix.sync.aligned.m8n8.x4.shared.b16 {%0,%1,%2,%3}, [%4];" \
                 : "=r"(r0), "=r"(r1), "=r"(r2), "=r"(r3) : "r"(addr))
// x2: one n-tile (lanes 0..15 addresses used)
#define LDSM_X2(r0, r1, addr) \
    asm volatile("ldmatrix.sync.aligned.m8n8.x2.shared.b16 {%0,%1}, [%2];" \
                 : "=r"(r0), "=r"(r1) : "r"(addr))

#define MMA_F16(c, a, b0, b1) \
    asm volatile("mma.sync.aligned.m16n8k16.row.col.f32.f16.f16.f32 " \
                 "{%0,%1,%2,%3}, {%4,%5,%6,%7}, {%8,%9}, {%0,%1,%2,%3};" \
                 : "+f"((c)[0]), "+f"((c)[1]), "+f"((c)[2]), "+f"((c)[3]) \
                 : "r"((a)[0]), "r"((a)[1]), "r"((a)[2]), "r"((a)[3]), "r"(b0), "r"(b1))

// split (v0,v1) -> packed hi f16x2 (round-nearest) and packed lo f16x2
// (residual). (hi + lo) represents v to ~22 mantissa bits.
__device__ __forceinline__ void split2h(float v0, float v1, uint32_t& hi, uint32_t& lo) {
    uint32_t h;
    asm("cvt.rn.f16x2.f32 %0, %1, %2;" : "=r"(h) : "f"(v1), "f"(v0));
    __half2 hh = *reinterpret_cast<__half2*>(&h);
    float f0 = __low2float(hh), f1 = __high2float(hh);
    uint32_t l;
    asm("cvt.rn.f16x2.f32 %0, %1, %2;" : "=r"(l) : "f"(v1 - f1), "f"(v0 - f0));
    hi = h; lo = l;
}

// One layer: acc[13][4] += (Ah+Al) @ W.  Per kt: 6 n-tile pairs via LDSM.x4
// (double-buffered) + 1 singleton (j=12) via LDSM.x2. Same-acc MMAs are
// dependency distance 2 apart within a pair.
template<int KT, int STRIDE>
__device__ __forceinline__ void mma_layer(float (&acc)[NT][4],
                                          const uint32_t (&Ah)[7][4],
                                          const uint32_t (&Al)[7][4],
                                          uint32_t wbase, uint32_t loff) {
    uint32_t B[2][4];
    #pragma unroll
    for (int kt = 0; kt < KT; kt++) {
        const uint32_t kb = wbase + (uint32_t)(kt * 32) + loff;
        LDSM_X4(B[0][0], B[0][1], B[0][2], B[0][3], kb);   // pair 0 (j=0,1)
        #pragma unroll
        for (int p = 0; p < 6; p++) {
            uint32_t (&cur)[4] = B[p & 1];
            uint32_t (&nxt)[4] = B[(p + 1) & 1];
            if (p < 5) {
                LDSM_X4(nxt[0], nxt[1], nxt[2], nxt[3],
                        kb + (uint32_t)((2 * (p + 1)) * 8 * STRIDE * 2));
            } else {
                LDSM_X2(nxt[0], nxt[1], kb + (uint32_t)(12 * 8 * STRIDE * 2));
            }
            const int j = 2 * p;
            MMA_F16(acc[j],     Ah[kt], cur[0], cur[1]);
            MMA_F16(acc[j + 1], Ah[kt], cur[2], cur[3]);
            MMA_F16(acc[j],     Al[kt], cur[0], cur[1]);
            MMA_F16(acc[j + 1], Al[kt], cur[2], cur[3]);
        }
        MMA_F16(acc[12], Ah[kt], B[0][0], B[0][1]);
        MMA_F16(acc[12], Al[kt], B[0][0], B[0][1]);
    }
}

// relu(acc + bias) -> next-layer A fragments (hi/lo fp16), reset acc.
__device__ __forceinline__ void build_A(float (&acc)[NT][4],
                                        uint32_t (&Ah)[7][4], uint32_t (&Al)[7][4],
                                        const float* bias, int m2) {
    #pragma unroll
    for (int j = 0; j < NT; j++) {
        float2 b = *reinterpret_cast<const float2*>(bias + 8 * j + m2);
        float v0 = fmaxf(acc[j][0] + b.x, 0.f);
        float v1 = fmaxf(acc[j][1] + b.y, 0.f);
        float v2 = fmaxf(acc[j][2] + b.x, 0.f);
        float v3 = fmaxf(acc[j][3] + b.y, 0.f);
        int kt = j >> 1, o = (j & 1) << 1;
        split2h(v0, v1, Ah[kt][o],     Al[kt][o]);
        split2h(v2, v3, Ah[kt][o + 1], Al[kt][o + 1]);
        acc[j][0] = acc[j][1] = acc[j][2] = acc[j][3] = 0.f;
    }
    Ah[6][2] = Ah[6][3] = Al[6][2] = Al[6][3] = 0u;  // k 104..111 pad
}

// Raw (ungated) gather of 32 values for a 16-row tile into registers.
__device__ __forceinline__ void gather_raw(float (&g)[32], const float* __restrict__ data,
                                           int wt, int n_rows, const int* sidx,
                                           int qrow, int m2) {
    const int r0 = wt * 16 + qrow;
    const int r1 = r0 + 8;
    const bool ok0 = r0 < n_rows, ok1 = r1 < n_rows;
    const float* dr0 = data + (size_t)(ok0 ? r0 : 0) * NNODE;
    const float* dr1 = data + (size_t)(ok1 ? r1 : 0) * NNODE;
    #pragma unroll
    for (int kt = 0; kt < 4; kt++) {
        int k0 = kt * 16 + m2;
        int i0 = sidx[k0], i1 = sidx[k0 + 1], i2 = sidx[k0 + 8], i3 = sidx[k0 + 9];
        g[kt * 8 + 0] = ok0 ? __ldg(dr0 + i0) : 0.f;
        g[kt * 8 + 1] = ok0 ? __ldg(dr0 + i1) : 0.f;
        g[kt * 8 + 2] = ok0 ? __ldg(dr0 + i2) : 0.f;
        g[kt * 8 + 3] = ok0 ? __ldg(dr0 + i3) : 0.f;
        g[kt * 8 + 4] = ok1 ? __ldg(dr1 + i0) : 0.f;
        g[kt * 8 + 5] = ok1 ? __ldg(dr1 + i1) : 0.f;
        g[kt * 8 + 6] = ok1 ? __ldg(dr1 + i2) : 0.f;
        g[kt * 8 + 7] = ok1 ? __ldg(dr1 + i3) : 0.f;
    }
}

extern __shared__ char sm[];

__global__ void __launch_bounds__(TPB, 1) nodal_mlp_hmma(
    const float* __restrict__ data, const float* __restrict__ weights,
    const float* __restrict__ W1, const float* __restrict__ b1,
    const float* __restrict__ W2, const float* __restrict__ b2,
    const float* __restrict__ W3, const float* __restrict__ b3,
    const float* __restrict__ W4, const float* __restrict__ b4,
    const int* __restrict__ data_idx, const int* __restrict__ edge_dir,
    const int* __restrict__ weight_idx,
    float* __restrict__ out, int n_rows)
{
    const int t = threadIdx.x;

    // ---- zero smem ----
    for (int i = t; i < SM_TOTAL / 4; i += TPB)
        reinterpret_cast<uint32_t*>(sm)[i] = 0;
    __syncthreads();

    // ---- sort indices: rank of each original k among data_idx (ties by pos) ----
    int* scr  = reinterpret_cast<int*>(sm + OFF_SCR);
    int* rnk  = reinterpret_cast<int*>(sm + OFF_RANK);
    if (t < AA) scr[t] = data_idx[t];
    __syncthreads();
    if (t < AA) {
        int my = scr[t];
        int r = 0;
        #pragma unroll
        for (int j = 0; j < AA; j++) {
            int o = scr[j];
            r += (o < my) || (o == my && j < t);
        }
        rnk[t] = r;
        reinterpret_cast<int*>(sm + OFF_IDX)[r] = my;
        float g = weights[weight_idx[t]] * (float)edge_dir[t];
        reinterpret_cast<float*>(sm + OFF_GATE)[r] = g > 0.f ? g : 0.f;
    }
    __syncthreads();

    // ---- stage weights once per CTA (single fp16); W1 rows permuted by rank ----
    for (int i = t; i < AA * HH; i += TPB) {
        int k = rnk[i / HH], n = i % HH;
        *reinterpret_cast<__half*>(sm + OFF_W1 + (n * W1S + k) * 2) = __float2half_rn(W1[i]);
    }
    for (int i = t; i < HH * HH; i += TPB) {
        int k = i / HH, n = i % HH;
        int o = (n * W2S + k) * 2;
        *reinterpret_cast<__half*>(sm + OFF_W2 + o) = __float2half_rn(W2[i]);
        *reinterpret_cast<__half*>(sm + OFF_W3 + o) = __float2half_rn(W3[i]);
    }
    if (t < HH) {
        reinterpret_cast<float*>(sm + OFF_B1)[t] = b1[t];
        reinterpret_cast<float*>(sm + OFF_B2)[t] = b2[t];
        reinterpret_cast<float*>(sm + OFF_B3)[t] = b3[t];
        reinterpret_cast<float*>(sm + OFF_W4)[t] = W4[t];
    }
    if (t == 0) reinterpret_cast<float*>(sm + OFF_B4)[0] = b4[0];
    __syncthreads();

    const uint32_t sb = smem_u32(sm);
    const int lane = t & 31;
    const int warp = t >> 5;
    const int m = lane & 3;
    const int m2 = m * 2;
    const int qrow = lane >> 2;
    // ldmatrix lane offsets: lanes 0-15 -> n-tile j (k, k+8), 16-31 -> n-tile j+1
    const uint32_t loff1 = (uint32_t)(((lane & 7) * W1S + ((lane >> 3) & 1) * 8) * 2
                                      + ((lane >> 4) & 1) * (8 * W1S * 2));
    const uint32_t loff2 = (uint32_t)(((lane & 7) * W2S + ((lane >> 3) & 1) * 8) * 2
                                      + ((lane >> 4) & 1) * (8 * W2S * 2));

    const float* gate = reinterpret_cast<const float*>(sm + OFF_GATE);
    const int*   sidx = reinterpret_cast<const int*>(sm + OFF_IDX);
    const float* sb1  = reinterpret_cast<const float*>(sm + OFF_B1);
    const float* sb2  = reinterpret_cast<const float*>(sm + OFF_B2);
    const float* sb3  = reinterpret_cast<const float*>(sm + OFF_B3);
    const float* sw4  = reinterpret_cast<const float*>(sm + OFF_W4);
    const float  b4v  = reinterpret_cast<const float*>(sm + OFF_B4)[0];

    const int n_wt = (n_rows + 15) >> 4;         // 16-row warp tiles
    const int gw = blockIdx.x * NWARP + warp;
    const int wstride = gridDim.x * NWARP;

    float g[32];
    if (gw < n_wt) gather_raw(g, data, gw, n_rows, sidx, qrow, m2);

    for (int wt = gw; wt < n_wt; wt += wstride) {
        const int r0 = wt * 16 + qrow;
        const int r1 = r0 + 8;
        const bool ok0 = r0 < n_rows, ok1 = r1 < n_rows;

        uint32_t Ah[7][4], Al[7][4];

        // ---- X fragments from prefetched raw values * gate ----
        #pragma unroll
        for (int kt = 0; kt < 4; kt++) {
            int k0 = kt * 16 + m2;
            float g0 = gate[k0], g1 = gate[k0 + 1], g2 = gate[k0 + 8], g3 = gate[k0 + 9];
            split2h(g[kt*8+0] * g0, g[kt*8+1] * g1, Ah[kt][0], Al[kt][0]);
            split2h(g[kt*8+4] * g0, g[kt*8+5] * g1, Ah[kt][1], Al[kt][1]);
            split2h(g[kt*8+2] * g2, g[kt*8+3] * g3, Ah[kt][2], Al[kt][2]);
            split2h(g[kt*8+6] * g2, g[kt*8+7] * g3, Ah[kt][3], Al[kt][3]);
        }

        float acc[NT][4];
        #pragma unroll
        for (int j = 0; j < NT; j++)
            acc[j][0] = acc[j][1] = acc[j][2] = acc[j][3] = 0.f;

        // ---- layer 1 ----
        mma_layer<4, W1S>(acc, Ah, Al, sb + OFF_W1, loff1);

        // ---- prefetch next tile's raw gather (hides under layers 2-3) ----
        const int nwt = wt + wstride;
        if (nwt < n_wt) gather_raw(g, data, nwt, n_rows, sidx, qrow, m2);

        build_A(acc, Ah, Al, sb1, m2);
        mma_layer<7, W2S>(acc, Ah, Al, sb + OFF_W2, loff2);
        build_A(acc, Ah, Al, sb2, m2);
        mma_layer<7, W2S>(acc, Ah, Al, sb + OFF_W3, loff2);

        // ---- layer 4: relu + dot + quad reduce ----
        float s0 = 0.f, s1 = 0.f;
        #pragma unroll
        for (int j = 0; j < NT; j++) {
            float2 b = *reinterpret_cast<const float2*>(sb3 + 8 * j + m2);
            float2 w = *reinterpret_cast<const float2*>(sw4 + 8 * j + m2);
            s0 = fmaf(fmaxf(acc[j][0] + b.x, 0.f), w.x, s0);
            s0 = fmaf(fmaxf(acc[j][1] + b.y, 0.f), w.y, s0);
            s1 = fmaf(fmaxf(acc[j][2] + b.x, 0.f), w.x, s1);
            s1 = fmaf(fmaxf(acc[j][3] + b.y, 0.f), w.y, s1);
        }
        s0 += __shfl_xor_sync(0xFFFFFFFFu, s0, 1);
        s0 += __shfl_xor_sync(0xFFFFFFFFu, s0, 2);
        s1 += __shfl_xor_sync(0xFFFFFFFFu, s1, 1);
        s1 += __shfl_xor_sync(0xFFFFFFFFu, s1, 2);
        if (m == 0) {
            if (ok0) out[r0] = s0 + b4v;
            if (ok1) out[r1] = s1 + b4v;
        }
    }
}

extern "C" void kernel_launch(void* const* d_in, const int* in_sizes, int n_in,
                              void* d_out, int out_size)
{
    const float* data       = (const float*)d_in[0];
    const float* weights    = (const float*)d_in[1];
    const float* W1         = (const float*)d_in[2];
    const float* b1         = (const float*)d_in[3];
    const float* W2         = (const float*)d_in[4];
    const float* b2         = (const float*)d_in[5];
    const float* W3         = (const float*)d_in[6];
    const float* b3         = (const float*)d_in[7];
    const float* W4         = (const float*)d_in[8];
    const float* b4         = (const float*)d_in[9];
    const int*   data_idx   = (const int*)d_in[10];
    const int*   edge_dir   = (const int*)d_in[11];
    const int*   weight_idx = (const int*)d_in[12];
    float* out = (float*)d_out;

    const int n_rows = out_size;

    cudaFuncSetAttribute(nodal_mlp_hmma,
                         cudaFuncAttributeMaxDynamicSharedMemorySize, SM_TOTAL);

    nodal_mlp_hmma<<<148, TPB, SM_TOTAL>>>(
        data, weights, W1, b1, W2, b2, W3, b3, W4, b4,
        data_idx, edge_dir, weight_idx, out, n_rows);
}

// round 17
// speedup vs baseline: 1.8155x; 1.1877x over previous
#include <cuda_runtime.h>
#include <cuda_fp16.h>
#include <cstdint>

// nodal_MLP via register-resident mma.sync, single-term fp16.
// A and W both rounded to fp16 (error ~2^-11 each; calibrated aggregate
// ~2.5e-4 vs 1e-3 gate). 1 MMA per (kt, n-tile). Sorted gather + prefetch,
// one W slab, LDSM.x4 feeds two n-tiles.

#define TPB    256
#define NWARP  8
#define NNODE  256
#define AA     64
#define HH     100
#define NT     13      // 13 n-tiles of 8 -> 104 (cols 100..103 zero-padded)
#define W1S    72      // k-stride (elems) for W1 slab: 64 + 8 pad
#define W2S    120     // k-stride for W2/W3: 112 + 8 pad

// SMEM byte offsets (all 16B aligned)
#define OFF_W1   0
#define W1_BYTES (104 * W1S * 2)        // 14976
#define OFF_W2   (OFF_W1 + W1_BYTES)
#define W2_BYTES (104 * W2S * 2)        // 24960
#define OFF_W3   (OFF_W2 + W2_BYTES)
#define OFF_B1   (OFF_W3 + W2_BYTES)    // 104 floats each
#define OFF_B2   (OFF_B1 + 416)
#define OFF_B3   (OFF_B2 + 416)
#define OFF_W4   (OFF_B3 + 416)
#define OFF_GATE (OFF_W4 + 416)         // 64 floats (sorted order)
#define OFF_IDX  (OFF_GATE + 256)       // 64 ints   (sorted order)
#define OFF_SCR  (OFF_IDX + 256)        // 64 ints raw idx scratch
#define OFF_RANK (OFF_SCR + 256)        // 64 ints: rank of original k
#define OFF_B4   (OFF_RANK + 256)
#define SM_TOTAL (OFF_B4 + 16)

__device__ __forceinline__ uint32_t smem_u32(const void* p) {
    uint32_t a;
    asm("{ .reg .u64 t; cvta.to.shared.u64 t, %1; cvt.u32.u64 %0, t; }" : "=r"(a) : "l"(p));
    return a;
}

// x4: 4 consecutive 8x8 b16 matrices = B fragments for TWO adjacent n-tiles.
#define LDSM_X4(r0, r1, r2, r3, addr) \
    asm volatile("ldmatrix.sync.aligned.m8n8.x4.shared.b16 {%0,%1,%2,%3}, [%4];" \
                 : "=r"(r0), "=r"(r1), "=r"(r2), "=r"(r3) : "r"(addr))
#define LDSM_X2(r0, r1, addr) \
    asm volatile("ldmatrix.sync.aligned.m8n8.x2.shared.b16 {%0,%1}, [%2];" \
                 : "=r"(r0), "=r"(r1) : "r"(addr))

#define MMA_F16(c, a, b0, b1) \
    asm volatile("mma.sync.aligned.m16n8k16.row.col.f32.f16.f16.f32 " \
                 "{%0,%1,%2,%3}, {%4,%5,%6,%7}, {%8,%9}, {%0,%1,%2,%3};" \
                 : "+f"((c)[0]), "+f"((c)[1]), "+f"((c)[2]), "+f"((c)[3]) \
                 : "r"((a)[0]), "r"((a)[1]), "r"((a)[2]), "r"((a)[3]), "r"(b0), "r"(b1))

__device__ __forceinline__ uint32_t packh2(float v0, float v1) {
    uint32_t h;
    asm("cvt.rn.f16x2.f32 %0, %1, %2;" : "=r"(h) : "f"(v1), "f"(v0));
    return h;
}

// One layer: acc[13][4] += A @ W (single fp16 term).
// Per kt: 6 n-tile pairs via LDSM.x4 (double-buffered) + 1 singleton.
template<int KT, int STRIDE>
__device__ __forceinline__ void mma_layer(float (&acc)[NT][4],
                                          const uint32_t (&Ah)[7][4],
                                          uint32_t wbase, uint32_t loff) {
    uint32_t B[2][4];
    #pragma unroll
    for (int kt = 0; kt < KT; kt++) {
        const uint32_t kb = wbase + (uint32_t)(kt * 32) + loff;
        LDSM_X4(B[0][0], B[0][1], B[0][2], B[0][3], kb);   // pair 0 (j=0,1)
        #pragma unroll
        for (int p = 0; p < 6; p++) {
            uint32_t (&cur)[4] = B[p & 1];
            uint32_t (&nxt)[4] = B[(p + 1) & 1];
            if (p < 5) {
                LDSM_X4(nxt[0], nxt[1], nxt[2], nxt[3],
                        kb + (uint32_t)((2 * (p + 1)) * 8 * STRIDE * 2));
            } else {
                LDSM_X2(nxt[0], nxt[1], kb + (uint32_t)(12 * 8 * STRIDE * 2));
            }
            const int j = 2 * p;
            MMA_F16(acc[j],     Ah[kt], cur[0], cur[1]);
            MMA_F16(acc[j + 1], Ah[kt], cur[2], cur[3]);
        }
        MMA_F16(acc[12], Ah[kt], B[0][0], B[0][1]);
    }
}

// relu(acc + bias) -> next-layer A fragments (fp16), reset acc.
__device__ __forceinline__ void build_A(float (&acc)[NT][4],
                                        uint32_t (&Ah)[7][4],
                                        const float* bias, int m2) {
    #pragma unroll
    for (int j = 0; j < NT; j++) {
        float2 b = *reinterpret_cast<const float2*>(bias + 8 * j + m2);
        float v0 = fmaxf(acc[j][0] + b.x, 0.f);
        float v1 = fmaxf(acc[j][1] + b.y, 0.f);
        float v2 = fmaxf(acc[j][2] + b.x, 0.f);
        float v3 = fmaxf(acc[j][3] + b.y, 0.f);
        int kt = j >> 1, o = (j & 1) << 1;
        Ah[kt][o]     = packh2(v0, v1);
        Ah[kt][o + 1] = packh2(v2, v3);
        acc[j][0] = acc[j][1] = acc[j][2] = acc[j][3] = 0.f;
    }
    Ah[6][2] = Ah[6][3] = 0u;  // k 104..111 pad
}

// Raw (ungated) gather of 32 values for a 16-row tile into registers.
__device__ __forceinline__ void gather_raw(float (&g)[32], const float* __restrict__ data,
                                           int wt, int n_rows, const int* sidx,
                                           int qrow, int m2) {
    const int r0 = wt * 16 + qrow;
    const int r1 = r0 + 8;
    const bool ok0 = r0 < n_rows, ok1 = r1 < n_rows;
    const float* dr0 = data + (size_t)(ok0 ? r0 : 0) * NNODE;
    const float* dr1 = data + (size_t)(ok1 ? r1 : 0) * NNODE;
    #pragma unroll
    for (int kt = 0; kt < 4; kt++) {
        int k0 = kt * 16 + m2;
        int i0 = sidx[k0], i1 = sidx[k0 + 1], i2 = sidx[k0 + 8], i3 = sidx[k0 + 9];
        g[kt * 8 + 0] = ok0 ? __ldg(dr0 + i0) : 0.f;
        g[kt * 8 + 1] = ok0 ? __ldg(dr0 + i1) : 0.f;
        g[kt * 8 + 2] = ok0 ? __ldg(dr0 + i2) : 0.f;
        g[kt * 8 + 3] = ok0 ? __ldg(dr0 + i3) : 0.f;
        g[kt * 8 + 4] = ok1 ? __ldg(dr1 + i0) : 0.f;
        g[kt * 8 + 5] = ok1 ? __ldg(dr1 + i1) : 0.f;
        g[kt * 8 + 6] = ok1 ? __ldg(dr1 + i2) : 0.f;
        g[kt * 8 + 7] = ok1 ? __ldg(dr1 + i3) : 0.f;
    }
}

extern __shared__ char sm[];

__global__ void __launch_bounds__(TPB, 1) nodal_mlp_hmma(
    const float* __restrict__ data, const float* __restrict__ weights,
    const float* __restrict__ W1, const float* __restrict__ b1,
    const float* __restrict__ W2, const float* __restrict__ b2,
    const float* __restrict__ W3, const float* __restrict__ b3,
    const float* __restrict__ W4, const float* __restrict__ b4,
    const int* __restrict__ data_idx, const int* __restrict__ edge_dir,
    const int* __restrict__ weight_idx,
    float* __restrict__ out, int n_rows)
{
    const int t = threadIdx.x;

    // ---- zero smem ----
    for (int i = t; i < SM_TOTAL / 4; i += TPB)
        reinterpret_cast<uint32_t*>(sm)[i] = 0;
    __syncthreads();

    // ---- sort indices: rank of each original k among data_idx (ties by pos) ----
    int* scr  = reinterpret_cast<int*>(sm + OFF_SCR);
    int* rnk  = reinterpret_cast<int*>(sm + OFF_RANK);
    if (t < AA) scr[t] = data_idx[t];
    __syncthreads();
    if (t < AA) {
        int my = scr[t];
        int r = 0;
        #pragma unroll
        for (int j = 0; j < AA; j++) {
            int o = scr[j];
            r += (o < my) || (o == my && j < t);
        }
        rnk[t] = r;
        reinterpret_cast<int*>(sm + OFF_IDX)[r] = my;
        float g = weights[weight_idx[t]] * (float)edge_dir[t];
        reinterpret_cast<float*>(sm + OFF_GATE)[r] = g > 0.f ? g : 0.f;
    }
    __syncthreads();

    // ---- stage weights once per CTA (fp16); W1 rows permuted by rank ----
    for (int i = t; i < AA * HH; i += TPB) {
        int k = rnk[i / HH], n = i % HH;
        *reinterpret_cast<__half*>(sm + OFF_W1 + (n * W1S + k) * 2) = __float2half_rn(W1[i]);
    }
    for (int i = t; i < HH * HH; i += TPB) {
        int k = i / HH, n = i % HH;
        int o = (n * W2S + k) * 2;
        *reinterpret_cast<__half*>(sm + OFF_W2 + o) = __float2half_rn(W2[i]);
        *reinterpret_cast<__half*>(sm + OFF_W3 + o) = __float2half_rn(W3[i]);
    }
    if (t < HH) {
        reinterpret_cast<float*>(sm + OFF_B1)[t] = b1[t];
        reinterpret_cast<float*>(sm + OFF_B2)[t] = b2[t];
        reinterpret_cast<float*>(sm + OFF_B3)[t] = b3[t];
        reinterpret_cast<float*>(sm + OFF_W4)[t] = W4[t];
    }
    if (t == 0) reinterpret_cast<float*>(sm + OFF_B4)[0] = b4[0];
    __syncthreads();

    const uint32_t sb = smem_u32(sm);
    const int lane = t & 31;
    const int warp = t >> 5;
    const int m = lane & 3;
    const int m2 = m * 2;
    const int qrow = lane >> 2;
    // ldmatrix lane offsets: lanes 0-15 -> n-tile j (k, k+8), 16-31 -> n-tile j+1
    const uint32_t loff1 = (uint32_t)(((lane & 7) * W1S + ((lane >> 3) & 1) * 8) * 2
                                      + ((lane >> 4) & 1) * (8 * W1S * 2));
    const uint32_t loff2 = (uint32_t)(((lane & 7) * W2S + ((lane >> 3) & 1) * 8) * 2
                                      + ((lane >> 4) & 1) * (8 * W2S * 2));

    const float* gate = reinterpret_cast<const float*>(sm + OFF_GATE);
    const int*   sidx = reinterpret_cast<const int*>(sm + OFF_IDX);
    const float* sb1  = reinterpret_cast<const float*>(sm + OFF_B1);
    const float* sb2  = reinterpret_cast<const float*>(sm + OFF_B2);
    const float* sb3  = reinterpret_cast<const float*>(sm + OFF_B3);
    const float* sw4  = reinterpret_cast<const float*>(sm + OFF_W4);
    const float  b4v  = reinterpret_cast<const float*>(sm + OFF_B4)[0];

    const int n_wt = (n_rows + 15) >> 4;         // 16-row warp tiles
    const int gw = blockIdx.x * NWARP + warp;
    const int wstride = gridDim.x * NWARP;

    float g[32];
    if (gw < n_wt) gather_raw(g, data, gw, n_rows, sidx, qrow, m2);

    for (int wt = gw; wt < n_wt; wt += wstride) {
        const int r0 = wt * 16 + qrow;
        const int r1 = r0 + 8;
        const bool ok0 = r0 < n_rows, ok1 = r1 < n_rows;

        uint32_t Ah[7][4];

        // ---- X fragments from prefetched raw values * gate ----
        #pragma unroll
        for (int kt = 0; kt < 4; kt++) {
            int k0 = kt * 16 + m2;
            float g0 = gate[k0], g1 = gate[k0 + 1], g2 = gate[k0 + 8], g3 = gate[k0 + 9];
            Ah[kt][0] = packh2(g[kt*8+0] * g0, g[kt*8+1] * g1);
            Ah[kt][1] = packh2(g[kt*8+4] * g0, g[kt*8+5] * g1);
            Ah[kt][2] = packh2(g[kt*8+2] * g2, g[kt*8+3] * g3);
            Ah[kt][3] = packh2(g[kt*8+6] * g2, g[kt*8+7] * g3);
        }

        float acc[NT][4];
        #pragma unroll
        for (int j = 0; j < NT; j++)
            acc[j][0] = acc[j][1] = acc[j][2] = acc[j][3] = 0.f;

        // ---- layer 1 ----
        mma_layer<4, W1S>(acc, Ah, sb + OFF_W1, loff1);

        // ---- prefetch next tile's raw gather (hides under layers 2-3) ----
        const int nwt = wt + wstride;
        if (nwt < n_wt) gather_raw(g, data, nwt, n_rows, sidx, qrow, m2);

        build_A(acc, Ah, sb1, m2);
        mma_layer<7, W2S>(acc, Ah, sb + OFF_W2, loff2);
        build_A(acc, Ah, sb2, m2);
        mma_layer<7, W2S>(acc, Ah, sb + OFF_W3, loff2);

        // ---- layer 4: relu + dot + quad reduce ----
        float s0 = 0.f, s1 = 0.f;
        #pragma unroll
        for (int j = 0; j < NT; j++) {
            float2 b = *reinterpret_cast<const float2*>(sb3 + 8 * j + m2);
            float2 w = *reinterpret_cast<const float2*>(sw4 + 8 * j + m2);
            s0 = fmaf(fmaxf(acc[j][0] + b.x, 0.f), w.x, s0);
            s0 = fmaf(fmaxf(acc[j][1] + b.y, 0.f), w.y, s0);
            s1 = fmaf(fmaxf(acc[j][2] + b.x, 0.f), w.x, s1);
            s1 = fmaf(fmaxf(acc[j][3] + b.y, 0.f), w.y, s1);
        }
        s0 += __shfl_xor_sync(0xFFFFFFFFu, s0, 1);
        s0 += __shfl_xor_sync(0xFFFFFFFFu, s0, 2);
        s1 += __shfl_xor_sync(0xFFFFFFFFu, s1, 1);
        s1 += __shfl_xor_sync(0xFFFFFFFFu, s1, 2);
        if (m == 0) {
            if (ok0) out[r0] = s0 + b4v;
            if (ok1) out[r1] = s1 + b4v;
        }
    }
}

extern "C" void kernel_launch(void* const* d_in, const int* in_sizes, int n_in,
                              void* d_out, int out_size)
{
    const float* data       = (const float*)d_in[0];
    const float* weights    = (const float*)d_in[1];
    const float* W1         = (const float*)d_in[2];
    const float* b1         = (const float*)d_in[3];
    const float* W2         = (const float*)d_in[4];
    const float* b2         = (const float*)d_in[5];
    const float* W3         = (const float*)d_in[6];
    const float* b3         = (const float*)d_in[7];
    const float* W4         = (const float*)d_in[8];
    const float* b4         = (const float*)d_in[9];
    const int*   data_idx   = (const int*)d_in[10];
    const int*   edge_dir   = (const int*)d_in[11];
    const int*   weight_idx = (const int*)d_in[12];
    float* out = (float*)d_out;

    const int n_rows = out_size;

    cudaFuncSetAttribute(nodal_mlp_hmma,
                         cudaFuncAttributeMaxDynamicSharedMemorySize, SM_TOTAL);

    nodal_mlp_hmma<<<148, TPB, SM_TOTAL>>>(
        data, weights, W1, b1, W2, b2, W3, b3, W4, b4,
        data_idx, edge_dir, weight_idx, out, n_rows);
}